// round 15
// baseline (speedup 1.0000x reference)
#include <cuda_runtime.h>
#include <cstdint>
#include <cstddef>

#define NB 32
#define NT 2048
#define ND 512
#define NROWS (NB*NT)   // 65536

// ---------------- scratch (static device arrays; no allocation) ----------------
__device__ float g_xn [(size_t)NROWS*ND];
__device__ float g_nh [(size_t)NROWS*ND];
__device__ float g_ifb[(size_t)NROWS*ND];
__device__ float g_h0 [(size_t)NROWS*ND];
__device__ float g_h1 [(size_t)NROWS*ND];

// ---------------- rmsnorm ----------------
__global__ __launch_bounds__(256) void rmsnorm_kernel(
    const float* __restrict__ x, const float* __restrict__ gamma,
    float* __restrict__ xn)
{
    int row = blockIdx.x * 8 + (threadIdx.x >> 5);
    int l = threadIdx.x & 31;
    const float4* xr = (const float4*)(x + (size_t)row * ND);
    const float4* gp = (const float4*)gamma;
    float4 v[4];
    float ss = 0.f;
#pragma unroll
    for (int i = 0; i < 4; i++) {
        v[i] = xr[l + 32*i];
        ss += v[i].x*v[i].x + v[i].y*v[i].y + v[i].z*v[i].z + v[i].w*v[i].w;
    }
#pragma unroll
    for (int o = 16; o > 0; o >>= 1) ss += __shfl_xor_sync(0xffffffffu, ss, o);
    float n = fmaxf(sqrtf(ss), 1e-12f);
    float s = 22.627416997969522f / n;
    float4* orow = (float4*)(xn + (size_t)row * ND);
#pragma unroll
    for (int i = 0; i < 4; i++) {
        float4 g4 = gp[l + 32*i];
        float4 o;
        o.x = v[i].x * s * (g4.x + 1.f);
        o.y = v[i].y * s * (g4.y + 1.f);
        o.z = v[i].z * s * (g4.z + 1.f);
        o.w = v[i].w * s * (g4.w + 1.f);
        orow[l + 32*i] = o;
    }
}

// ---------------- bf16 tensor-core GEMM (proven ~0.28ms): C = A @ W ----------------
__device__ __forceinline__ uint32_t fpack_bf(float lo, float hi) {
    uint32_t u; asm("cvt.rn.bf16x2.f32 %0, %1, %2;" : "=r"(u) : "f"(hi), "f"(lo)); return u;
}
__device__ __forceinline__ void mma_bf16(float c[4], const uint32_t a[4], const uint32_t b[2]) {
    asm volatile(
        "mma.sync.aligned.m16n8k16.row.col.f32.bf16.bf16.f32 "
        "{%0,%1,%2,%3},{%4,%5,%6,%7},{%8,%9},{%0,%1,%2,%3};"
        : "+f"(c[0]), "+f"(c[1]), "+f"(c[2]), "+f"(c[3])
        : "r"(a[0]), "r"(a[1]), "r"(a[2]), "r"(a[3]), "r"(b[0]), "r"(b[1]));
}

// Shared mainloop: computes 128x128 tile of A@W into acc.
// EPI==0: store (opt tanh) to C.  EPI==1: fused gate-combine epilogue.
template<int ACT, int EPI>
__global__ __launch_bounds__(256) void tgemm_kernel(
    const float* __restrict__ A, const float* __restrict__ W,
    float* __restrict__ C,
    const float* __restrict__ xg, const float* __restrict__ nhg,
    const float* __restrict__ ifbg, const float* __restrict__ bhfg)
{
    __shared__ uint32_t As2[2][8][136];
    __shared__ uint32_t Bs2[2][8][136];
    const int tid = threadIdx.x;
    const int l   = tid & 31;
    const int wid = tid >> 5;
    const int wm  = wid & 3;
    const int wn  = wid >> 2;
    const int gid = l >> 2, tig = l & 3;

    const int am  = tid >> 1;
    const int akp = (tid & 1) * 4;
    const int bkp = tid >> 5;
    const int bn  = (tid & 31) * 4;

    const float* Ap  = A + ((size_t)blockIdx.x * 128 + am) * ND + akp * 2;
    const float* Wp0 = W + (size_t)(2 * bkp) * ND + blockIdx.y * 128 + bn;
    const float* Wp1 = Wp0 + ND;

    float acc[2][8][4];
#pragma unroll
    for (int mt = 0; mt < 2; mt++)
#pragma unroll
        for (int nt = 0; nt < 8; nt++)
#pragma unroll
            for (int e = 0; e < 4; e++) acc[mt][nt][e] = 0.f;

    float4 pa0 = *(const float4*)(Ap);
    float4 pa1 = *(const float4*)(Ap + 4);
    float4 pb0 = *(const float4*)(Wp0);
    float4 pb1 = *(const float4*)(Wp1);

    {
        As2[0][akp+0][am] = fpack_bf(pa0.x, pa0.y);
        As2[0][akp+1][am] = fpack_bf(pa0.z, pa0.w);
        As2[0][akp+2][am] = fpack_bf(pa1.x, pa1.y);
        As2[0][akp+3][am] = fpack_bf(pa1.z, pa1.w);
        uint4 u = make_uint4(fpack_bf(pb0.x, pb1.x), fpack_bf(pb0.y, pb1.y),
                             fpack_bf(pb0.z, pb1.z), fpack_bf(pb0.w, pb1.w));
        *(uint4*)&Bs2[0][bkp][bn] = u;
    }
    __syncthreads();

    for (int kt = 0; kt < 32; kt++) {
        const int cur = kt & 1;
        if (kt < 31) {
            const int k0 = (kt + 1) * 16;
            pa0 = *(const float4*)(Ap + k0);
            pa1 = *(const float4*)(Ap + k0 + 4);
            pb0 = *(const float4*)(Wp0 + (size_t)k0 * ND);
            pb1 = *(const float4*)(Wp1 + (size_t)k0 * ND);
        }
        {
            uint32_t af[2][4], bf[8][2];
#pragma unroll
            for (int mt = 0; mt < 2; mt++) {
                int m0 = wm * 32 + mt * 16 + gid;
                af[mt][0] = As2[cur][tig][m0];
                af[mt][1] = As2[cur][tig][m0 + 8];
                af[mt][2] = As2[cur][tig + 4][m0];
                af[mt][3] = As2[cur][tig + 4][m0 + 8];
            }
#pragma unroll
            for (int nt = 0; nt < 8; nt++) {
                int n0 = wn * 64 + nt * 8 + gid;
                bf[nt][0] = Bs2[cur][tig][n0];
                bf[nt][1] = Bs2[cur][tig + 4][n0];
            }
#pragma unroll
            for (int mt = 0; mt < 2; mt++)
#pragma unroll
                for (int nt = 0; nt < 8; nt++)
                    mma_bf16(acc[mt][nt], af[mt], bf[nt]);
        }
        if (kt < 31) {
            const int nxt = cur ^ 1;
            As2[nxt][akp+0][am] = fpack_bf(pa0.x, pa0.y);
            As2[nxt][akp+1][am] = fpack_bf(pa0.z, pa0.w);
            As2[nxt][akp+2][am] = fpack_bf(pa1.x, pa1.y);
            As2[nxt][akp+3][am] = fpack_bf(pa1.z, pa1.w);
            uint4 u = make_uint4(fpack_bf(pb0.x, pb1.x), fpack_bf(pb0.y, pb1.y),
                                 fpack_bf(pb0.z, pb1.z), fpack_bf(pb0.w, pb1.w));
            *(uint4*)&Bs2[nxt][bkp][bn] = u;
        }
        __syncthreads();
    }

#pragma unroll
    for (int mt = 0; mt < 2; mt++) {
        int row = blockIdx.x * 128 + wm * 32 + mt * 16 + gid;
#pragma unroll
        for (int nt = 0; nt < 8; nt++) {
            int col = blockIdx.y * 128 + wn * 64 + nt * 8 + tig * 2;
            if (EPI == 0) {
                float v0 = acc[mt][nt][0], v1 = acc[mt][nt][1];
                float v2 = acc[mt][nt][2], v3 = acc[mt][nt][3];
                if (ACT == 1) { v0 = tanhf(v0); v1 = tanhf(v1); v2 = tanhf(v2); v3 = tanhf(v3); }
                *(float2*)(C + (size_t)row * ND + col)       = make_float2(v0, v1);
                *(float2*)(C + (size_t)(row + 8) * ND + col) = make_float2(v2, v3);
            } else {
                float2 bh = *(const float2*)(bhfg + col);
#pragma unroll
                for (int rr = 0; rr < 2; rr++) {
                    size_t off = (size_t)(row + rr * 8) * ND + col;
                    float2 xv  = *(const float2*)(xg + off);
                    float2 xnv = *(const float2*)(A + off);      // A == xn
                    float2 nhv = *(const float2*)(nhg + off);
                    float2 iv  = *(const float2*)(ifbg + off);
                    float hf0 = acc[mt][nt][rr*2], hf1 = acc[mt][nt][rr*2+1];
                    float z0 = hf0 + bh.x + iv.x;
                    float z1 = hf1 + bh.y + iv.y;
                    float g0 = 1.f / (1.f + __expf(-z0));
                    float g1 = 1.f / (1.f + __expf(-z1));
                    float2 o;
                    o.x = xv.x + xnv.x + g0 * (nhv.x - xnv.x);
                    o.y = xv.y + xnv.y + g1 * (nhv.y - xnv.y);
                    *(float2*)(C + off) = o;
                }
            }
        }
    }
}

// ---------------- sequential LRU scan, v9 ----------------
// v8 skeleton with W residency shift: chunks 0..7 fp32 regs, 8..11 bf16x2 REGS,
// only 12..15 in bf16 smem (32KB/step crossbar, was 64KB). Slot rotation
// ((c-12)+l)&3 in 64B/thread blocks (quad-bank verified conflict-free).
__global__ __launch_bounds__(512, 1) void scan_kernel(
    const float* __restrict__ nh, const float* __restrict__ ifg,
    const float* __restrict__ Whf, const float* __restrict__ bhf,
    float* __restrict__ hout)
{
    extern __shared__ float smem[];   // [0,32KB): bf16 W (4 chunks); [32KB,+4KB): h
    char*  wsm  = (char*)smem;
    float* hbuf = (float*)((char*)smem + 32768);

    const int rank  = blockIdx.x & 3;
    const int batch = blockIdx.x >> 2;
    const int tid = threadIdx.x;
    const int w = tid >> 5;
    const int l = tid & 31;
    const int jc = rank * 128 + w * 8;
    const int rot = rank * 4;

    // fp32 register W: logical c=0..7 -> physical p=(rot+c)&15, k = l+32p
    unsigned long long Wreg[8][4];
#pragma unroll
    for (int c = 0; c < 8; c++) {
        const int p = (rot + c) & 15;
        const float* pw = Whf + (size_t)(l + 32*p) * ND + jc;
        float4 a = *(const float4*)pw;
        float4 b = *(const float4*)(pw + 4);
        asm("mov.b64 %0,{%1,%2};" : "=l"(Wreg[c][0]) : "f"(a.x), "f"(a.y));
        asm("mov.b64 %0,{%1,%2};" : "=l"(Wreg[c][1]) : "f"(a.z), "f"(a.w));
        asm("mov.b64 %0,{%1,%2};" : "=l"(Wreg[c][2]) : "f"(b.x), "f"(b.y));
        asm("mov.b64 %0,{%1,%2};" : "=l"(Wreg[c][3]) : "f"(b.z), "f"(b.w));
    }
    // bf16 register W: logical c=8..11 -> physical p=(rot+c)&15
    uint32_t Wbf[4][4];
#pragma unroll
    for (int c = 8; c < 12; c++) {
        const int p = (rot + c) & 15;
        const float* pw = Whf + (size_t)(l + 32*p) * ND + jc;
        float4 a = *(const float4*)pw;
        float4 b = *(const float4*)(pw + 4);
        Wbf[c-8][0] = fpack_bf(a.x, a.y);
        Wbf[c-8][1] = fpack_bf(a.z, a.w);
        Wbf[c-8][2] = fpack_bf(b.x, b.y);
        Wbf[c-8][3] = fpack_bf(b.z, b.w);
    }
    // bf16 smem W: logical c=12..15 -> physical p=(rot+c)&15, slot ((c-12)+l)&3
    const uint32_t wbase = (uint32_t)__cvta_generic_to_shared(wsm) + (uint32_t)tid * 64u;
#pragma unroll
    for (int c = 12; c < 16; c++) {
        const int p = (rot + c) & 15;
        const float* pw = Whf + (size_t)(l + 32*p) * ND + jc;
        float4 a = *(const float4*)pw;
        float4 b = *(const float4*)(pw + 4);
        uint32_t u0 = fpack_bf(a.x, a.y), u1 = fpack_bf(a.z, a.w);
        uint32_t u2 = fpack_bf(b.x, b.y), u3 = fpack_bf(b.z, b.w);
        asm volatile("st.shared.v4.b32 [%0], {%1,%2,%3,%4};"
                     :: "r"(wbase + (uint32_t)((((c - 12) + l) & 3) * 16)),
                        "r"(u0), "r"(u1), "r"(u2), "r"(u3) : "memory");
    }
    hbuf[tid] = 0.f;
    hbuf[tid + 512] = 0.f;

    const uint32_t hbase = (uint32_t)__cvta_generic_to_shared(hbuf);

    const int isProd = ((l & 3) == 0);
    const int j = jc + (l >> 2);
    float bj = 0.f, h_prev = 0.f;
    const float *nhp = nullptr, *ifp = nullptr;
    float* hop = nullptr;
    uint32_t raddr[2][3];
    if (isProd) {
        bj = bhf[j];
        size_t off = (size_t)batch * NT * ND + j;
        nhp = nh + off; ifp = ifg + off; hop = hout + off;
#pragma unroll
        for (int buf = 0; buf < 2; buf++) {
            uint32_t la = hbase + (uint32_t)((buf * 512 + j) * 4);
#pragma unroll
            for (int rr = 0; rr < 3; rr++) {
                int tgt = (rank + 1 + rr) & 3;
                asm("mapa.shared::cluster.u32 %0, %1, %2;"
                    : "=r"(raddr[buf][rr]) : "r"(la), "r"(tgt));
            }
        }
    }

    asm volatile("barrier.cluster.arrive.aligned;" ::: "memory");
    asm volatile("barrier.cluster.wait.aligned;"   ::: "memory");

    float nh_cur = 0.f, if_cur = 0.f;
    if (isProd) { nh_cur = nhp[0]; if_cur = ifp[0]; }

    const bool hi16 = (l & 16) != 0;
    const bool hi8  = (l & 8)  != 0;
    const bool hi4  = (l & 4)  != 0;

    unsigned long long accA0 = 0ull, accA1 = 0ull, accA2 = 0ull, accA3 = 0ull;

    asm volatile("barrier.cluster.arrive.aligned;" ::: "memory");   // open pipeline

    for (int t = 0; t < NT; t++) {
        const int cur = t & 1, nxt = cur ^ 1;
        float nh_nxt = 0.f, if_nxt = 0.f;
        if (isProd && t + 1 < NT) {
            nh_nxt = nhp[(size_t)(t+1) * ND];
            if_nxt = ifp[(size_t)(t+1) * ND];
        }
        asm volatile("barrier.cluster.wait.aligned;" ::: "memory");   // h[cur] complete

        const float* hr = hbuf + cur * 512;
        unsigned long long a01 = accA0, a23 = accA1, a45 = accA2, a67 = accA3;
        // phase B1: fp32 register chunks c=4..7
#pragma unroll
        for (int c = 4; c < 8; c++) {
            float hk = hr[(l + 32 * ((rot + c) & 15))];
            unsigned long long hd;
            asm("mov.b64 %0,{%1,%1};" : "=l"(hd) : "f"(hk));
            asm volatile("fma.rn.f32x2 %0, %1, %2, %0;" : "+l"(a01) : "l"(hd), "l"(Wreg[c][0]));
            asm volatile("fma.rn.f32x2 %0, %1, %2, %0;" : "+l"(a23) : "l"(hd), "l"(Wreg[c][1]));
            asm volatile("fma.rn.f32x2 %0, %1, %2, %0;" : "+l"(a45) : "l"(hd), "l"(Wreg[c][2]));
            asm volatile("fma.rn.f32x2 %0, %1, %2, %0;" : "+l"(a67) : "l"(hd), "l"(Wreg[c][3]));
        }
        // phase B2: bf16 register chunks c=8..11
#pragma unroll
        for (int c = 8; c < 12; c++) {
            float hk = hr[(l + 32 * ((rot + c) & 15))];
            unsigned long long hd;
            asm("mov.b64 %0,{%1,%1};" : "=l"(hd) : "f"(hk));
            unsigned long long w0, w1, w2, w3;
            asm("{.reg .b32 lo,hi; shl.b32 lo,%1,16; and.b32 hi,%1,0xffff0000U; mov.b64 %0,{lo,hi};}"
                : "=l"(w0) : "r"(Wbf[c-8][0]));
            asm("{.reg .b32 lo,hi; shl.b32 lo,%1,16; and.b32 hi,%1,0xffff0000U; mov.b64 %0,{lo,hi};}"
                : "=l"(w1) : "r"(Wbf[c-8][1]));
            asm("{.reg .b32 lo,hi; shl.b32 lo,%1,16; and.b32 hi,%1,0xffff0000U; mov.b64 %0,{lo,hi};}"
                : "=l"(w2) : "r"(Wbf[c-8][2]));
            asm("{.reg .b32 lo,hi; shl.b32 lo,%1,16; and.b32 hi,%1,0xffff0000U; mov.b64 %0,{lo,hi};}"
                : "=l"(w3) : "r"(Wbf[c-8][3]));
            asm volatile("fma.rn.f32x2 %0, %1, %2, %0;" : "+l"(a01) : "l"(hd), "l"(w0));
            asm volatile("fma.rn.f32x2 %0, %1, %2, %0;" : "+l"(a23) : "l"(hd), "l"(w1));
            asm volatile("fma.rn.f32x2 %0, %1, %2, %0;" : "+l"(a45) : "l"(hd), "l"(w2));
            asm volatile("fma.rn.f32x2 %0, %1, %2, %0;" : "+l"(a67) : "l"(hd), "l"(w3));
        }
        // phase B3: bf16 smem chunks c=12..15
#pragma unroll
        for (int c = 12; c < 16; c++) {
            float hk = hr[(l + 32 * ((rot + c) & 15))];
            unsigned long long hd;
            asm("mov.b64 %0,{%1,%1};" : "=l"(hd) : "f"(hk));
            uint32_t u0, u1, u2, u3;
            asm volatile("ld.shared.v4.b32 {%0,%1,%2,%3},[%4];"
                         : "=r"(u0), "=r"(u1), "=r"(u2), "=r"(u3)
                         : "r"(wbase + (uint32_t)((((c - 12) + l) & 3) * 16)));
            unsigned long long w0, w1, w2, w3;
            asm("{.reg .b32 lo,hi; shl.b32 lo,%1,16; and.b32 hi,%1,0xffff0000U; mov.b64 %0,{lo,hi};}"
                : "=l"(w0) : "r"(u0));
            asm("{.reg .b32 lo,hi; shl.b32 lo,%1,16; and.b32 hi,%1,0xffff0000U; mov.b64 %0,{lo,hi};}"
                : "=l"(w1) : "r"(u1));
            asm("{.reg .b32 lo,hi; shl.b32 lo,%1,16; and.b32 hi,%1,0xffff0000U; mov.b64 %0,{lo,hi};}"
                : "=l"(w2) : "r"(u2));
            asm("{.reg .b32 lo,hi; shl.b32 lo,%1,16; and.b32 hi,%1,0xffff0000U; mov.b64 %0,{lo,hi};}"
                : "=l"(w3) : "r"(u3));
            asm volatile("fma.rn.f32x2 %0, %1, %2, %0;" : "+l"(a01) : "l"(hd), "l"(w0));
            asm volatile("fma.rn.f32x2 %0, %1, %2, %0;" : "+l"(a23) : "l"(hd), "l"(w1));
            asm volatile("fma.rn.f32x2 %0, %1, %2, %0;" : "+l"(a45) : "l"(hd), "l"(w2));
            asm volatile("fma.rn.f32x2 %0, %1, %2, %0;" : "+l"(a67) : "l"(hd), "l"(w3));
        }
        float a0,a1,a2,a3,a4,a5,a6,a7;
        asm("mov.b64 {%0,%1},%2;" : "=f"(a0), "=f"(a1) : "l"(a01));
        asm("mov.b64 {%0,%1},%2;" : "=f"(a2), "=f"(a3) : "l"(a23));
        asm("mov.b64 {%0,%1},%2;" : "=f"(a4), "=f"(a5) : "l"(a45));
        asm("mov.b64 {%0,%1},%2;" : "=f"(a6), "=f"(a7) : "l"(a67));
        float b0, b1, b2, b3;
        {
            float s0 = hi16 ? a0 : a4, k0 = hi16 ? a4 : a0;
            float s1 = hi16 ? a1 : a5, k1 = hi16 ? a5 : a1;
            float s2 = hi16 ? a2 : a6, k2 = hi16 ? a6 : a2;
            float s3 = hi16 ? a3 : a7, k3 = hi16 ? a7 : a3;
            b0 = k0 + __shfl_xor_sync(0xffffffffu, s0, 16);
            b1 = k1 + __shfl_xor_sync(0xffffffffu, s1, 16);
            b2 = k2 + __shfl_xor_sync(0xffffffffu, s2, 16);
            b3 = k3 + __shfl_xor_sync(0xffffffffu, s3, 16);
        }
        float d0, d1;
        {
            float s0 = hi8 ? b0 : b2, k0 = hi8 ? b2 : b0;
            float s1 = hi8 ? b1 : b3, k1 = hi8 ? b3 : b1;
            d0 = k0 + __shfl_xor_sync(0xffffffffu, s0, 8);
            d1 = k1 + __shfl_xor_sync(0xffffffffu, s1, 8);
        }
        float e;
        {
            float s = hi4 ? d0 : d1, k = hi4 ? d1 : d0;
            e = k + __shfl_xor_sync(0xffffffffu, s, 4);
        }
        e += __shfl_xor_sync(0xffffffffu, e, 2);
        e += __shfl_xor_sync(0xffffffffu, e, 1);

        float hn = 0.f;
        if (isProd) {
            float z = e + bj + if_cur;
            float g = 1.f / (1.f + __expf(-z));
            hn = fmaf(g, nh_cur - h_prev, h_prev);
            h_prev = hn;
            hbuf[nxt * 512 + j] = hn;   // local (plain STS, syncthreads-ordered)
            asm volatile("st.shared::cluster.f32 [%0], %1;" :: "r"(raddr[nxt][0]), "f"(hn) : "memory");
            asm volatile("st.shared::cluster.f32 [%0], %1;" :: "r"(raddr[nxt][1]), "f"(hn) : "memory");
            asm volatile("st.shared::cluster.f32 [%0], %1;" :: "r"(raddr[nxt][2]), "f"(hn) : "memory");
        }
        asm volatile("barrier.cluster.arrive.aligned;" ::: "memory");
        if (isProd) hop[(size_t)t * ND] = hn;
        nh_cur = nh_nxt; if_cur = if_nxt;
        __syncthreads();   // local h[nxt] visible
        // phase A for step t+1: local chunks c=0..3 (k in [128*rank, 128*rank+128))
        {
            const float* hn_loc = hbuf + nxt * 512;
            accA0 = 0ull; accA1 = 0ull; accA2 = 0ull; accA3 = 0ull;
#pragma unroll
            for (int c = 0; c < 4; c++) {
                float hk = hn_loc[(l + 32 * ((rot + c) & 15))];
                unsigned long long hd;
                asm("mov.b64 %0,{%1,%1};" : "=l"(hd) : "f"(hk));
                asm volatile("fma.rn.f32x2 %0, %1, %2, %0;" : "+l"(accA0) : "l"(hd), "l"(Wreg[c][0]));
                asm volatile("fma.rn.f32x2 %0, %1, %2, %0;" : "+l"(accA1) : "l"(hd), "l"(Wreg[c][1]));
                asm volatile("fma.rn.f32x2 %0, %1, %2, %0;" : "+l"(accA2) : "l"(hd), "l"(Wreg[c][2]));
                asm volatile("fma.rn.f32x2 %0, %1, %2, %0;" : "+l"(accA3) : "l"(hd), "l"(Wreg[c][3]));
            }
        }
    }
    asm volatile("barrier.cluster.wait.aligned;" ::: "memory");   // match final arrive
}

// ---------------- launch ----------------
static void launch_scan(const float* nh, const float* ifb,
                        const float* W, const float* b, float* ho)
{
    constexpr int SMEMB = 32768 + 4096;
    cudaFuncSetAttribute(scan_kernel, cudaFuncAttributeMaxDynamicSharedMemorySize, SMEMB);
    cudaLaunchConfig_t cfg = {};
    cfg.gridDim  = dim3(128, 1, 1);
    cfg.blockDim = dim3(512, 1, 1);
    cfg.dynamicSmemBytes = SMEMB;
    cfg.stream = 0;
    cudaLaunchAttribute attr;
    attr.id = cudaLaunchAttributeClusterDimension;
    attr.val.clusterDim.x = 4; attr.val.clusterDim.y = 1; attr.val.clusterDim.z = 1;
    cfg.attrs = &attr;
    cfg.numAttrs = 1;
    cudaLaunchKernelEx(&cfg, scan_kernel, nh, ifb, W, b, ho);
}

extern "C" void kernel_launch(void* const* d_in, const int* in_sizes, int n_in,
                              void* d_out, int out_size)
{
    const float* x     = (const float*)d_in[0];
    const float* gamma = (const float*)d_in[1];
    const float* gWn   = (const float*)d_in[2];
    const float* gWif  = (const float*)d_in[3];
    const float* gWhf  = (const float*)d_in[4];
    const float* gbhf  = (const float*)d_in[5];
    const float* l0Wn  = (const float*)d_in[6];
    const float* l0Wif = (const float*)d_in[7];
    const float* l0Whf = (const float*)d_in[8];
    const float* l0bhf = (const float*)d_in[9];
    const float* l1Wn  = (const float*)d_in[10];
    const float* l1Wif = (const float*)d_in[11];
    const float* l1Whf = (const float*)d_in[12];
    const float* l1bhf = (const float*)d_in[13];
    float* out = (float*)d_out;

    float *xn, *nh, *ifb, *h0, *h1;
    cudaGetSymbolAddress((void**)&xn,  g_xn);
    cudaGetSymbolAddress((void**)&nh,  g_nh);
    cudaGetSymbolAddress((void**)&ifb, g_ifb);
    cudaGetSymbolAddress((void**)&h0,  g_h0);
    cudaGetSymbolAddress((void**)&h1,  g_h1);

    dim3 gg(NROWS / 128, ND / 128);

    rmsnorm_kernel<<<NROWS / 8, 256>>>(x, gamma, xn);

    tgemm_kernel<1,0><<<gg, 256>>>(xn, l0Wn,  nh,  nullptr, nullptr, nullptr, nullptr);
    tgemm_kernel<0,0><<<gg, 256>>>(xn, l0Wif, ifb, nullptr, nullptr, nullptr, nullptr);
    launch_scan(nh, ifb, l0Whf, l0bhf, h0);

    tgemm_kernel<1,0><<<gg, 256>>>(h0, l1Wn,  nh,  nullptr, nullptr, nullptr, nullptr);
    tgemm_kernel<0,0><<<gg, 256>>>(h0, l1Wif, ifb, nullptr, nullptr, nullptr, nullptr);
    launch_scan(nh, ifb, l1Whf, l1bhf, h1);

    tgemm_kernel<1,0><<<gg, 256>>>(h1, gWn,  nh,  nullptr, nullptr, nullptr, nullptr);
    tgemm_kernel<0,0><<<gg, 256>>>(h1, gWif, ifb, nullptr, nullptr, nullptr, nullptr);
    // fused: hf = xn @ gWhf computed in-register; epilogue does gate-combine + residual
    tgemm_kernel<0,1><<<gg, 256>>>(xn, gWhf, out, x, nh, ifb, gbhf);
}

// round 16
// speedup vs baseline: 1.0066x; 1.0066x over previous
#include <cuda_runtime.h>
#include <cstdint>
#include <cstddef>

#define NB 32
#define NT 2048
#define ND 512
#define NROWS (NB*NT)   // 65536

// ---------------- scratch (static device arrays; no allocation) ----------------
__device__ float g_xn [(size_t)NROWS*ND];
__device__ float g_nh [(size_t)NROWS*ND];
__device__ float g_ifb[(size_t)NROWS*ND];
__device__ float g_h0 [(size_t)NROWS*ND];
__device__ float g_h1 [(size_t)NROWS*ND];

// ---------------- rmsnorm ----------------
__global__ __launch_bounds__(256) void rmsnorm_kernel(
    const float* __restrict__ x, const float* __restrict__ gamma,
    float* __restrict__ xn)
{
    int row = blockIdx.x * 8 + (threadIdx.x >> 5);
    int l = threadIdx.x & 31;
    const float4* xr = (const float4*)(x + (size_t)row * ND);
    const float4* gp = (const float4*)gamma;
    float4 v[4];
    float ss = 0.f;
#pragma unroll
    for (int i = 0; i < 4; i++) {
        v[i] = xr[l + 32*i];
        ss += v[i].x*v[i].x + v[i].y*v[i].y + v[i].z*v[i].z + v[i].w*v[i].w;
    }
#pragma unroll
    for (int o = 16; o > 0; o >>= 1) ss += __shfl_xor_sync(0xffffffffu, ss, o);
    float n = fmaxf(sqrtf(ss), 1e-12f);
    float s = 22.627416997969522f / n;
    float4* orow = (float4*)(xn + (size_t)row * ND);
#pragma unroll
    for (int i = 0; i < 4; i++) {
        float4 g4 = gp[l + 32*i];
        float4 o;
        o.x = v[i].x * s * (g4.x + 1.f);
        o.y = v[i].y * s * (g4.y + 1.f);
        o.z = v[i].z * s * (g4.z + 1.f);
        o.w = v[i].w * s * (g4.w + 1.f);
        orow[l + 32*i] = o;
    }
}

// ---------------- bf16 tensor-core GEMM (proven ~0.28ms): C = A @ W ----------------
__device__ __forceinline__ uint32_t fpack_bf(float lo, float hi) {
    uint32_t u; asm("cvt.rn.bf16x2.f32 %0, %1, %2;" : "=r"(u) : "f"(hi), "f"(lo)); return u;
}
__device__ __forceinline__ void mma_bf16(float c[4], const uint32_t a[4], const uint32_t b[2]) {
    asm volatile(
        "mma.sync.aligned.m16n8k16.row.col.f32.bf16.bf16.f32 "
        "{%0,%1,%2,%3},{%4,%5,%6,%7},{%8,%9},{%0,%1,%2,%3};"
        : "+f"(c[0]), "+f"(c[1]), "+f"(c[2]), "+f"(c[3])
        : "r"(a[0]), "r"(a[1]), "r"(a[2]), "r"(a[3]), "r"(b[0]), "r"(b[1]));
}

// Shared mainloop: computes 128x128 tile of A@W into acc.
// EPI==0: store (opt tanh) to C.  EPI==1: fused gate-combine epilogue.
template<int ACT, int EPI>
__global__ __launch_bounds__(256) void tgemm_kernel(
    const float* __restrict__ A, const float* __restrict__ W,
    float* __restrict__ C,
    const float* __restrict__ xg, const float* __restrict__ nhg,
    const float* __restrict__ ifbg, const float* __restrict__ bhfg)
{
    __shared__ uint32_t As2[2][8][136];
    __shared__ uint32_t Bs2[2][8][136];
    const int tid = threadIdx.x;
    const int l   = tid & 31;
    const int wid = tid >> 5;
    const int wm  = wid & 3;
    const int wn  = wid >> 2;
    const int gid = l >> 2, tig = l & 3;

    const int am  = tid >> 1;
    const int akp = (tid & 1) * 4;
    const int bkp = tid >> 5;
    const int bn  = (tid & 31) * 4;

    const float* Ap  = A + ((size_t)blockIdx.x * 128 + am) * ND + akp * 2;
    const float* Wp0 = W + (size_t)(2 * bkp) * ND + blockIdx.y * 128 + bn;
    const float* Wp1 = Wp0 + ND;

    float acc[2][8][4];
#pragma unroll
    for (int mt = 0; mt < 2; mt++)
#pragma unroll
        for (int nt = 0; nt < 8; nt++)
#pragma unroll
            for (int e = 0; e < 4; e++) acc[mt][nt][e] = 0.f;

    float4 pa0 = *(const float4*)(Ap);
    float4 pa1 = *(const float4*)(Ap + 4);
    float4 pb0 = *(const float4*)(Wp0);
    float4 pb1 = *(const float4*)(Wp1);

    {
        As2[0][akp+0][am] = fpack_bf(pa0.x, pa0.y);
        As2[0][akp+1][am] = fpack_bf(pa0.z, pa0.w);
        As2[0][akp+2][am] = fpack_bf(pa1.x, pa1.y);
        As2[0][akp+3][am] = fpack_bf(pa1.z, pa1.w);
        uint4 u = make_uint4(fpack_bf(pb0.x, pb1.x), fpack_bf(pb0.y, pb1.y),
                             fpack_bf(pb0.z, pb1.z), fpack_bf(pb0.w, pb1.w));
        *(uint4*)&Bs2[0][bkp][bn] = u;
    }
    __syncthreads();

    for (int kt = 0; kt < 32; kt++) {
        const int cur = kt & 1;
        if (kt < 31) {
            const int k0 = (kt + 1) * 16;
            pa0 = *(const float4*)(Ap + k0);
            pa1 = *(const float4*)(Ap + k0 + 4);
            pb0 = *(const float4*)(Wp0 + (size_t)k0 * ND);
            pb1 = *(const float4*)(Wp1 + (size_t)k0 * ND);
        }
        {
            uint32_t af[2][4], bf[8][2];
#pragma unroll
            for (int mt = 0; mt < 2; mt++) {
                int m0 = wm * 32 + mt * 16 + gid;
                af[mt][0] = As2[cur][tig][m0];
                af[mt][1] = As2[cur][tig][m0 + 8];
                af[mt][2] = As2[cur][tig + 4][m0];
                af[mt][3] = As2[cur][tig + 4][m0 + 8];
            }
#pragma unroll
            for (int nt = 0; nt < 8; nt++) {
                int n0 = wn * 64 + nt * 8 + gid;
                bf[nt][0] = Bs2[cur][tig][n0];
                bf[nt][1] = Bs2[cur][tig + 4][n0];
            }
#pragma unroll
            for (int mt = 0; mt < 2; mt++)
#pragma unroll
                for (int nt = 0; nt < 8; nt++)
                    mma_bf16(acc[mt][nt], af[mt], bf[nt]);
        }
        if (kt < 31) {
            const int nxt = cur ^ 1;
            As2[nxt][akp+0][am] = fpack_bf(pa0.x, pa0.y);
            As2[nxt][akp+1][am] = fpack_bf(pa0.z, pa0.w);
            As2[nxt][akp+2][am] = fpack_bf(pa1.x, pa1.y);
            As2[nxt][akp+3][am] = fpack_bf(pa1.z, pa1.w);
            uint4 u = make_uint4(fpack_bf(pb0.x, pb1.x), fpack_bf(pb0.y, pb1.y),
                                 fpack_bf(pb0.z, pb1.z), fpack_bf(pb0.w, pb1.w));
            *(uint4*)&Bs2[nxt][bkp][bn] = u;
        }
        __syncthreads();
    }

#pragma unroll
    for (int mt = 0; mt < 2; mt++) {
        int row = blockIdx.x * 128 + wm * 32 + mt * 16 + gid;
#pragma unroll
        for (int nt = 0; nt < 8; nt++) {
            int col = blockIdx.y * 128 + wn * 64 + nt * 8 + tig * 2;
            if (EPI == 0) {
                float v0 = acc[mt][nt][0], v1 = acc[mt][nt][1];
                float v2 = acc[mt][nt][2], v3 = acc[mt][nt][3];
                if (ACT == 1) { v0 = tanhf(v0); v1 = tanhf(v1); v2 = tanhf(v2); v3 = tanhf(v3); }
                *(float2*)(C + (size_t)row * ND + col)       = make_float2(v0, v1);
                *(float2*)(C + (size_t)(row + 8) * ND + col) = make_float2(v2, v3);
            } else {
                float2 bh = *(const float2*)(bhfg + col);
#pragma unroll
                for (int rr = 0; rr < 2; rr++) {
                    size_t off = (size_t)(row + rr * 8) * ND + col;
                    float2 xv  = *(const float2*)(xg + off);
                    float2 xnv = *(const float2*)(A + off);      // A == xn
                    float2 nhv = *(const float2*)(nhg + off);
                    float2 iv  = *(const float2*)(ifbg + off);
                    float hf0 = acc[mt][nt][rr*2], hf1 = acc[mt][nt][rr*2+1];
                    float z0 = hf0 + bh.x + iv.x;
                    float z1 = hf1 + bh.y + iv.y;
                    float g0 = 1.f / (1.f + __expf(-z0));
                    float g1 = 1.f / (1.f + __expf(-z1));
                    float2 o;
                    o.x = xv.x + xnv.x + g0 * (nhv.x - xnv.x);
                    o.y = xv.y + xnv.y + g1 * (nhv.y - xnv.y);
                    *(float2*)(C + off) = o;
                }
            }
        }
    }
}

// ---------------- sequential LRU scan, v10 ----------------
// R14/v8 skeleton (8 fp32-reg chunks + 8 bf16-smem chunks, barrier-shadow
// phase A, rank-rotated chunk map), with h stored PRE-DUPLICATED as b64 {h,h}:
// all h loads feed fma.rn.f32x2 directly (deletes ~20 ALU movs/thread/step).
__global__ __launch_bounds__(512, 1) void scan_kernel(
    const float* __restrict__ nh, const float* __restrict__ ifg,
    const float* __restrict__ Whf, const float* __restrict__ bhf,
    float* __restrict__ hout)
{
    extern __shared__ float smem[];   // [0,64KB): bf16 W half; [64KB,+8KB): h dup double buf
    char* wsm = (char*)smem;
    unsigned long long* hbuf = (unsigned long long*)((char*)smem + 65536);

    const int rank  = blockIdx.x & 3;
    const int batch = blockIdx.x >> 2;
    const int tid = threadIdx.x;
    const int w = tid >> 5;
    const int l = tid & 31;
    const int jc = rank * 128 + w * 8;
    const int rot = rank * 4;

    // register W: logical c=0..7 -> physical chunk p=(rot+c)&15, k = l+32p
    unsigned long long Wreg[8][4];
#pragma unroll
    for (int c = 0; c < 8; c++) {
        const int p = (rot + c) & 15;
        const float* pw = Whf + (size_t)(l + 32*p) * ND + jc;
        float4 a = *(const float4*)pw;
        float4 b = *(const float4*)(pw + 4);
        asm("mov.b64 %0,{%1,%2};" : "=l"(Wreg[c][0]) : "f"(a.x), "f"(a.y));
        asm("mov.b64 %0,{%1,%2};" : "=l"(Wreg[c][1]) : "f"(a.z), "f"(a.w));
        asm("mov.b64 %0,{%1,%2};" : "=l"(Wreg[c][2]) : "f"(b.x), "f"(b.y));
        asm("mov.b64 %0,{%1,%2};" : "=l"(Wreg[c][3]) : "f"(b.z), "f"(b.w));
    }
    // smem bf16 W: logical c=8..15 -> physical p=(rot+c)&15, slot ((c-8)+l)&7
    const uint32_t wbase = (uint32_t)__cvta_generic_to_shared(wsm) + (uint32_t)tid * 128u;
#pragma unroll
    for (int c = 8; c < 16; c++) {
        const int p = (rot + c) & 15;
        const float* pw = Whf + (size_t)(l + 32*p) * ND + jc;
        float4 a = *(const float4*)pw;
        float4 b = *(const float4*)(pw + 4);
        uint32_t u0 = fpack_bf(a.x, a.y), u1 = fpack_bf(a.z, a.w);
        uint32_t u2 = fpack_bf(b.x, b.y), u3 = fpack_bf(b.z, b.w);
        asm volatile("st.shared.v4.b32 [%0], {%1,%2,%3,%4};"
                     :: "r"(wbase + (uint32_t)((((c - 8) + l) & 7) * 16)),
                        "r"(u0), "r"(u1), "r"(u2), "r"(u3) : "memory");
    }
    hbuf[tid] = 0ull;
    hbuf[tid + 512] = 0ull;

    const uint32_t hbase = (uint32_t)__cvta_generic_to_shared(hbuf);

    const int isProd = ((l & 3) == 0);
    const int j = jc + (l >> 2);
    float bj = 0.f, h_prev = 0.f;
    const float *nhp = nullptr, *ifp = nullptr;
    float* hop = nullptr;
    uint32_t raddr[2][3];   // remote ranks only (local uses plain STS)
    if (isProd) {
        bj = bhf[j];
        size_t off = (size_t)batch * NT * ND + j;
        nhp = nh + off; ifp = ifg + off; hop = hout + off;
#pragma unroll
        for (int buf = 0; buf < 2; buf++) {
            uint32_t la = hbase + (uint32_t)((buf * 512 + j) * 8);
#pragma unroll
            for (int rr = 0; rr < 3; rr++) {
                int tgt = (rank + 1 + rr) & 3;
                asm("mapa.shared::cluster.u32 %0, %1, %2;"
                    : "=r"(raddr[buf][rr]) : "r"(la), "r"(tgt));
            }
        }
    }

    asm volatile("barrier.cluster.arrive.aligned;" ::: "memory");
    asm volatile("barrier.cluster.wait.aligned;"   ::: "memory");

    float nh_cur = 0.f, if_cur = 0.f;
    if (isProd) { nh_cur = nhp[0]; if_cur = ifp[0]; }

    const bool hi16 = (l & 16) != 0;
    const bool hi8  = (l & 8)  != 0;
    const bool hi4  = (l & 4)  != 0;

    // phase-A carry for step 0: h = 0 -> zero partials
    unsigned long long accA0 = 0ull, accA1 = 0ull, accA2 = 0ull, accA3 = 0ull;

    asm volatile("barrier.cluster.arrive.aligned;" ::: "memory");   // open pipeline

    for (int t = 0; t < NT; t++) {
        const int cur = t & 1, nxt = cur ^ 1;
        float nh_nxt = 0.f, if_nxt = 0.f;
        if (isProd && t + 1 < NT) {
            nh_nxt = nhp[(size_t)(t+1) * ND];
            if_nxt = ifp[(size_t)(t+1) * ND];
        }
        asm volatile("barrier.cluster.wait.aligned;" ::: "memory");   // h[cur] complete

        const uint32_t hcur = hbase + (uint32_t)(cur * 4096);
        unsigned long long a01 = accA0, a23 = accA1, a45 = accA2, a67 = accA3;
        // phase B: register chunks c=4..7 (h as direct b64 load)
#pragma unroll
        for (int c = 4; c < 8; c++) {
            unsigned long long hd;
            asm volatile("ld.shared.b64 %0,[%1];"
                         : "=l"(hd) : "r"(hcur + (uint32_t)((l + 32 * ((rot + c) & 15)) * 8)));
            asm volatile("fma.rn.f32x2 %0, %1, %2, %0;" : "+l"(a01) : "l"(hd), "l"(Wreg[c][0]));
            asm volatile("fma.rn.f32x2 %0, %1, %2, %0;" : "+l"(a23) : "l"(hd), "l"(Wreg[c][1]));
            asm volatile("fma.rn.f32x2 %0, %1, %2, %0;" : "+l"(a45) : "l"(hd), "l"(Wreg[c][2]));
            asm volatile("fma.rn.f32x2 %0, %1, %2, %0;" : "+l"(a67) : "l"(hd), "l"(Wreg[c][3]));
        }
        // phase B: smem bf16 chunks c=8..15
#pragma unroll
        for (int c = 8; c < 16; c++) {
            unsigned long long hd;
            asm volatile("ld.shared.b64 %0,[%1];"
                         : "=l"(hd) : "r"(hcur + (uint32_t)((l + 32 * ((rot + c) & 15)) * 8)));
            uint32_t u0, u1, u2, u3;
            asm volatile("ld.shared.v4.b32 {%0,%1,%2,%3},[%4];"
                         : "=r"(u0), "=r"(u1), "=r"(u2), "=r"(u3)
                         : "r"(wbase + (uint32_t)((((c - 8) + l) & 7) * 16)));
            unsigned long long w0, w1, w2, w3;
            asm("{.reg .b32 lo,hi; shl.b32 lo,%1,16; and.b32 hi,%1,0xffff0000U; mov.b64 %0,{lo,hi};}"
                : "=l"(w0) : "r"(u0));
            asm("{.reg .b32 lo,hi; shl.b32 lo,%1,16; and.b32 hi,%1,0xffff0000U; mov.b64 %0,{lo,hi};}"
                : "=l"(w1) : "r"(u1));
            asm("{.reg .b32 lo,hi; shl.b32 lo,%1,16; and.b32 hi,%1,0xffff0000U; mov.b64 %0,{lo,hi};}"
                : "=l"(w2) : "r"(u2));
            asm("{.reg .b32 lo,hi; shl.b32 lo,%1,16; and.b32 hi,%1,0xffff0000U; mov.b64 %0,{lo,hi};}"
                : "=l"(w3) : "r"(u3));
            asm volatile("fma.rn.f32x2 %0, %1, %2, %0;" : "+l"(a01) : "l"(hd), "l"(w0));
            asm volatile("fma.rn.f32x2 %0, %1, %2, %0;" : "+l"(a23) : "l"(hd), "l"(w1));
            asm volatile("fma.rn.f32x2 %0, %1, %2, %0;" : "+l"(a45) : "l"(hd), "l"(w2));
            asm volatile("fma.rn.f32x2 %0, %1, %2, %0;" : "+l"(a67) : "l"(hd), "l"(w3));
        }
        float a0,a1,a2,a3,a4,a5,a6,a7;
        asm("mov.b64 {%0,%1},%2;" : "=f"(a0), "=f"(a1) : "l"(a01));
        asm("mov.b64 {%0,%1},%2;" : "=f"(a2), "=f"(a3) : "l"(a23));
        asm("mov.b64 {%0,%1},%2;" : "=f"(a4), "=f"(a5) : "l"(a45));
        asm("mov.b64 {%0,%1},%2;" : "=f"(a6), "=f"(a7) : "l"(a67));
        float b0, b1, b2, b3;
        {
            float s0 = hi16 ? a0 : a4, k0 = hi16 ? a4 : a0;
            float s1 = hi16 ? a1 : a5, k1 = hi16 ? a5 : a1;
            float s2 = hi16 ? a2 : a6, k2 = hi16 ? a6 : a2;
            float s3 = hi16 ? a3 : a7, k3 = hi16 ? a7 : a3;
            b0 = k0 + __shfl_xor_sync(0xffffffffu, s0, 16);
            b1 = k1 + __shfl_xor_sync(0xffffffffu, s1, 16);
            b2 = k2 + __shfl_xor_sync(0xffffffffu, s2, 16);
            b3 = k3 + __shfl_xor_sync(0xffffffffu, s3, 16);
        }
        float d0, d1;
        {
            float s0 = hi8 ? b0 : b2, k0 = hi8 ? b2 : b0;
            float s1 = hi8 ? b1 : b3, k1 = hi8 ? b3 : b1;
            d0 = k0 + __shfl_xor_sync(0xffffffffu, s0, 8);
            d1 = k1 + __shfl_xor_sync(0xffffffffu, s1, 8);
        }
        float e;
        {
            float s = hi4 ? d0 : d1, k = hi4 ? d1 : d0;
            e = k + __shfl_xor_sync(0xffffffffu, s, 4);
        }
        e += __shfl_xor_sync(0xffffffffu, e, 2);
        e += __shfl_xor_sync(0xffffffffu, e, 1);

        float hn = 0.f;
        if (isProd) {
            float z = e + bj + if_cur;
            float g = 1.f / (1.f + __expf(-z));
            hn = fmaf(g, nh_cur - h_prev, h_prev);
            h_prev = hn;
            unsigned long long hd;
            asm("mov.b64 %0,{%1,%1};" : "=l"(hd) : "f"(hn));
            hbuf[nxt * 512 + j] = hd;   // local (plain STS, syncthreads-ordered)
            asm volatile("st.shared::cluster.b64 [%0], %1;" :: "r"(raddr[nxt][0]), "l"(hd) : "memory");
            asm volatile("st.shared::cluster.b64 [%0], %1;" :: "r"(raddr[nxt][1]), "l"(hd) : "memory");
            asm volatile("st.shared::cluster.b64 [%0], %1;" :: "r"(raddr[nxt][2]), "l"(hd) : "memory");
        }
        asm volatile("barrier.cluster.arrive.aligned;" ::: "memory");
        if (isProd) hop[(size_t)t * ND] = hn;
        nh_cur = nh_nxt; if_cur = if_nxt;
        __syncthreads();   // local h[nxt] visible
        // phase A for step t+1: local chunks c=0..3 (k in [128*rank, 128*rank+128))
        {
            const uint32_t hnb = hbase + (uint32_t)(nxt * 4096);
            accA0 = 0ull; accA1 = 0ull; accA2 = 0ull; accA3 = 0ull;
#pragma unroll
            for (int c = 0; c < 4; c++) {
                unsigned long long hd;
                asm volatile("ld.shared.b64 %0,[%1];"
                             : "=l"(hd) : "r"(hnb + (uint32_t)((l + 32 * ((rot + c) & 15)) * 8)));
                asm volatile("fma.rn.f32x2 %0, %1, %2, %0;" : "+l"(accA0) : "l"(hd), "l"(Wreg[c][0]));
                asm volatile("fma.rn.f32x2 %0, %1, %2, %0;" : "+l"(accA1) : "l"(hd), "l"(Wreg[c][1]));
                asm volatile("fma.rn.f32x2 %0, %1, %2, %0;" : "+l"(accA2) : "l"(hd), "l"(Wreg[c][2]));
                asm volatile("fma.rn.f32x2 %0, %1, %2, %0;" : "+l"(accA3) : "l"(hd), "l"(Wreg[c][3]));
            }
        }
    }
    asm volatile("barrier.cluster.wait.aligned;" ::: "memory");   // match final arrive
}

// ---------------- launch ----------------
static void launch_scan(const float* nh, const float* ifb,
                        const float* W, const float* b, float* ho)
{
    constexpr int SMEMB = 65536 + 8192;
    cudaFuncSetAttribute(scan_kernel, cudaFuncAttributeMaxDynamicSharedMemorySize, SMEMB);
    cudaLaunchConfig_t cfg = {};
    cfg.gridDim  = dim3(128, 1, 1);
    cfg.blockDim = dim3(512, 1, 1);
    cfg.dynamicSmemBytes = SMEMB;
    cfg.stream = 0;
    cudaLaunchAttribute attr;
    attr.id = cudaLaunchAttributeClusterDimension;
    attr.val.clusterDim.x = 4; attr.val.clusterDim.y = 1; attr.val.clusterDim.z = 1;
    cfg.attrs = &attr;
    cfg.numAttrs = 1;
    cudaLaunchKernelEx(&cfg, scan_kernel, nh, ifb, W, b, ho);
}

extern "C" void kernel_launch(void* const* d_in, const int* in_sizes, int n_in,
                              void* d_out, int out_size)
{
    const float* x     = (const float*)d_in[0];
    const float* gamma = (const float*)d_in[1];
    const float* gWn   = (const float*)d_in[2];
    const float* gWif  = (const float*)d_in[3];
    const float* gWhf  = (const float*)d_in[4];
    const float* gbhf  = (const float*)d_in[5];
    const float* l0Wn  = (const float*)d_in[6];
    const float* l0Wif = (const float*)d_in[7];
    const float* l0Whf = (const float*)d_in[8];
    const float* l0bhf = (const float*)d_in[9];
    const float* l1Wn  = (const float*)d_in[10];
    const float* l1Wif = (const float*)d_in[11];
    const float* l1Whf = (const float*)d_in[12];
    const float* l1bhf = (const float*)d_in[13];
    float* out = (float*)d_out;

    float *xn, *nh, *ifb, *h0, *h1;
    cudaGetSymbolAddress((void**)&xn,  g_xn);
    cudaGetSymbolAddress((void**)&nh,  g_nh);
    cudaGetSymbolAddress((void**)&ifb, g_ifb);
    cudaGetSymbolAddress((void**)&h0,  g_h0);
    cudaGetSymbolAddress((void**)&h1,  g_h1);

    dim3 gg(NROWS / 128, ND / 128);

    rmsnorm_kernel<<<NROWS / 8, 256>>>(x, gamma, xn);

    tgemm_kernel<1,0><<<gg, 256>>>(xn, l0Wn,  nh,  nullptr, nullptr, nullptr, nullptr);
    tgemm_kernel<0,0><<<gg, 256>>>(xn, l0Wif, ifb, nullptr, nullptr, nullptr, nullptr);
    launch_scan(nh, ifb, l0Whf, l0bhf, h0);

    tgemm_kernel<1,0><<<gg, 256>>>(h0, l1Wn,  nh,  nullptr, nullptr, nullptr, nullptr);
    tgemm_kernel<0,0><<<gg, 256>>>(h0, l1Wif, ifb, nullptr, nullptr, nullptr, nullptr);
    launch_scan(nh, ifb, l1Whf, l1bhf, h1);

    tgemm_kernel<1,0><<<gg, 256>>>(h1, gWn,  nh,  nullptr, nullptr, nullptr, nullptr);
    tgemm_kernel<0,0><<<gg, 256>>>(h1, gWif, ifb, nullptr, nullptr, nullptr, nullptr);
    // fused: hf = xn @ gWhf computed in-register; epilogue does gate-combine + residual
    tgemm_kernel<0,1><<<gg, 256>>>(xn, gWhf, out, x, nh, ifb, gbhf);
}

// round 17
// speedup vs baseline: 1.0648x; 1.0578x over previous
#include <cuda_runtime.h>
#include <cstdint>
#include <cstddef>

#define NB 32
#define NT 2048
#define ND 512
#define NROWS (NB*NT)   // 65536

// ---------------- scratch (static device arrays; no allocation) ----------------
__device__ float g_xn [(size_t)NROWS*ND];
__device__ float g_nh [(size_t)NROWS*ND];
__device__ float g_ifb[(size_t)NROWS*ND];
__device__ float g_h0 [(size_t)NROWS*ND];
__device__ float g_h1 [(size_t)NROWS*ND];

// ---------------- rmsnorm ----------------
__global__ __launch_bounds__(256) void rmsnorm_kernel(
    const float* __restrict__ x, const float* __restrict__ gamma,
    float* __restrict__ xn)
{
    int row = blockIdx.x * 8 + (threadIdx.x >> 5);
    int l = threadIdx.x & 31;
    const float4* xr = (const float4*)(x + (size_t)row * ND);
    const float4* gp = (const float4*)gamma;
    float4 v[4];
    float ss = 0.f;
#pragma unroll
    for (int i = 0; i < 4; i++) {
        v[i] = xr[l + 32*i];
        ss += v[i].x*v[i].x + v[i].y*v[i].y + v[i].z*v[i].z + v[i].w*v[i].w;
    }
#pragma unroll
    for (int o = 16; o > 0; o >>= 1) ss += __shfl_xor_sync(0xffffffffu, ss, o);
    float n = fmaxf(sqrtf(ss), 1e-12f);
    float s = 22.627416997969522f / n;
    float4* orow = (float4*)(xn + (size_t)row * ND);
#pragma unroll
    for (int i = 0; i < 4; i++) {
        float4 g4 = gp[l + 32*i];
        float4 o;
        o.x = v[i].x * s * (g4.x + 1.f);
        o.y = v[i].y * s * (g4.y + 1.f);
        o.z = v[i].z * s * (g4.z + 1.f);
        o.w = v[i].w * s * (g4.w + 1.f);
        orow[l + 32*i] = o;
    }
}

// ---------------- bf16 tensor-core GEMM (proven ~0.28ms): C = A @ W ----------------
__device__ __forceinline__ uint32_t fpack_bf(float lo, float hi) {
    uint32_t u; asm("cvt.rn.bf16x2.f32 %0, %1, %2;" : "=r"(u) : "f"(hi), "f"(lo)); return u;
}
__device__ __forceinline__ void mma_bf16(float c[4], const uint32_t a[4], const uint32_t b[2]) {
    asm volatile(
        "mma.sync.aligned.m16n8k16.row.col.f32.bf16.bf16.f32 "
        "{%0,%1,%2,%3},{%4,%5,%6,%7},{%8,%9},{%0,%1,%2,%3};"
        : "+f"(c[0]), "+f"(c[1]), "+f"(c[2]), "+f"(c[3])
        : "r"(a[0]), "r"(a[1]), "r"(a[2]), "r"(a[3]), "r"(b[0]), "r"(b[1]));
}

// Shared mainloop: computes 128x128 tile of A@W into acc.
// EPI==0: store (opt tanh) to C.  EPI==1: fused gate-combine epilogue.
template<int ACT, int EPI>
__global__ __launch_bounds__(256) void tgemm_kernel(
    const float* __restrict__ A, const float* __restrict__ W,
    float* __restrict__ C,
    const float* __restrict__ xg, const float* __restrict__ nhg,
    const float* __restrict__ ifbg, const float* __restrict__ bhfg)
{
    __shared__ uint32_t As2[2][8][136];
    __shared__ uint32_t Bs2[2][8][136];
    const int tid = threadIdx.x;
    const int l   = tid & 31;
    const int wid = tid >> 5;
    const int wm  = wid & 3;
    const int wn  = wid >> 2;
    const int gid = l >> 2, tig = l & 3;

    const int am  = tid >> 1;
    const int akp = (tid & 1) * 4;
    const int bkp = tid >> 5;
    const int bn  = (tid & 31) * 4;

    const float* Ap  = A + ((size_t)blockIdx.x * 128 + am) * ND + akp * 2;
    const float* Wp0 = W + (size_t)(2 * bkp) * ND + blockIdx.y * 128 + bn;
    const float* Wp1 = Wp0 + ND;

    float acc[2][8][4];
#pragma unroll
    for (int mt = 0; mt < 2; mt++)
#pragma unroll
        for (int nt = 0; nt < 8; nt++)
#pragma unroll
            for (int e = 0; e < 4; e++) acc[mt][nt][e] = 0.f;

    float4 pa0 = *(const float4*)(Ap);
    float4 pa1 = *(const float4*)(Ap + 4);
    float4 pb0 = *(const float4*)(Wp0);
    float4 pb1 = *(const float4*)(Wp1);

    {
        As2[0][akp+0][am] = fpack_bf(pa0.x, pa0.y);
        As2[0][akp+1][am] = fpack_bf(pa0.z, pa0.w);
        As2[0][akp+2][am] = fpack_bf(pa1.x, pa1.y);
        As2[0][akp+3][am] = fpack_bf(pa1.z, pa1.w);
        uint4 u = make_uint4(fpack_bf(pb0.x, pb1.x), fpack_bf(pb0.y, pb1.y),
                             fpack_bf(pb0.z, pb1.z), fpack_bf(pb0.w, pb1.w));
        *(uint4*)&Bs2[0][bkp][bn] = u;
    }
    __syncthreads();

    for (int kt = 0; kt < 32; kt++) {
        const int cur = kt & 1;
        if (kt < 31) {
            const int k0 = (kt + 1) * 16;
            pa0 = *(const float4*)(Ap + k0);
            pa1 = *(const float4*)(Ap + k0 + 4);
            pb0 = *(const float4*)(Wp0 + (size_t)k0 * ND);
            pb1 = *(const float4*)(Wp1 + (size_t)k0 * ND);
        }
        {
            uint32_t af[2][4], bf[8][2];
#pragma unroll
            for (int mt = 0; mt < 2; mt++) {
                int m0 = wm * 32 + mt * 16 + gid;
                af[mt][0] = As2[cur][tig][m0];
                af[mt][1] = As2[cur][tig][m0 + 8];
                af[mt][2] = As2[cur][tig + 4][m0];
                af[mt][3] = As2[cur][tig + 4][m0 + 8];
            }
#pragma unroll
            for (int nt = 0; nt < 8; nt++) {
                int n0 = wn * 64 + nt * 8 + gid;
                bf[nt][0] = Bs2[cur][tig][n0];
                bf[nt][1] = Bs2[cur][tig + 4][n0];
            }
#pragma unroll
            for (int mt = 0; mt < 2; mt++)
#pragma unroll
                for (int nt = 0; nt < 8; nt++)
                    mma_bf16(acc[mt][nt], af[mt], bf[nt]);
        }
        if (kt < 31) {
            const int nxt = cur ^ 1;
            As2[nxt][akp+0][am] = fpack_bf(pa0.x, pa0.y);
            As2[nxt][akp+1][am] = fpack_bf(pa0.z, pa0.w);
            As2[nxt][akp+2][am] = fpack_bf(pa1.x, pa1.y);
            As2[nxt][akp+3][am] = fpack_bf(pa1.z, pa1.w);
            uint4 u = make_uint4(fpack_bf(pb0.x, pb1.x), fpack_bf(pb0.y, pb1.y),
                                 fpack_bf(pb0.z, pb1.z), fpack_bf(pb0.w, pb1.w));
            *(uint4*)&Bs2[nxt][bkp][bn] = u;
        }
        __syncthreads();
    }

#pragma unroll
    for (int mt = 0; mt < 2; mt++) {
        int row = blockIdx.x * 128 + wm * 32 + mt * 16 + gid;
#pragma unroll
        for (int nt = 0; nt < 8; nt++) {
            int col = blockIdx.y * 128 + wn * 64 + nt * 8 + tig * 2;
            if (EPI == 0) {
                float v0 = acc[mt][nt][0], v1 = acc[mt][nt][1];
                float v2 = acc[mt][nt][2], v3 = acc[mt][nt][3];
                if (ACT == 1) { v0 = tanhf(v0); v1 = tanhf(v1); v2 = tanhf(v2); v3 = tanhf(v3); }
                *(float2*)(C + (size_t)row * ND + col)       = make_float2(v0, v1);
                *(float2*)(C + (size_t)(row + 8) * ND + col) = make_float2(v2, v3);
            } else {
                float2 bh = *(const float2*)(bhfg + col);
#pragma unroll
                for (int rr = 0; rr < 2; rr++) {
                    size_t off = (size_t)(row + rr * 8) * ND + col;
                    float2 xv  = *(const float2*)(xg + off);
                    float2 xnv = *(const float2*)(A + off);      // A == xn
                    float2 nhv = *(const float2*)(nhg + off);
                    float2 iv  = *(const float2*)(ifbg + off);
                    float hf0 = acc[mt][nt][rr*2], hf1 = acc[mt][nt][rr*2+1];
                    float z0 = hf0 + bh.x + iv.x;
                    float z1 = hf1 + bh.y + iv.y;
                    float g0 = 1.f / (1.f + __expf(-z0));
                    float g1 = 1.f / (1.f + __expf(-z1));
                    float2 o;
                    o.x = xv.x + xnv.x + g0 * (nhv.x - xnv.x);
                    o.y = xv.y + xnv.y + g1 * (nhv.y - xnv.y);
                    *(float2*)(C + off) = o;
                }
            }
        }
    }
}

// ---------------- sequential LRU scan, v11 ----------------
// R14/v8 base (8 fp32-reg chunks + 8 bf16-smem chunks, barrier-shadow phase A,
// rank-rotated chunk map, fp32 h buffer) with quad-redundant gate: all 4 quad
// lanes hold the full column sum after reduction, each lane stores hn to ONE
// cluster rank (sub 0 local STS, subs 1-3 one remote store each) -> the serial
// 4-store producer tail becomes 2 instructions.
__global__ __launch_bounds__(512, 1) void scan_kernel(
    const float* __restrict__ nh, const float* __restrict__ ifg,
    const float* __restrict__ Whf, const float* __restrict__ bhf,
    float* __restrict__ hout)
{
    extern __shared__ float smem[];   // [0,64KB): bf16 W half; [64KB,+4KB): h double buf
    char*  wsm  = (char*)smem;
    float* hbuf = (float*)((char*)smem + 65536);

    const int rank  = blockIdx.x & 3;
    const int batch = blockIdx.x >> 2;
    const int tid = threadIdx.x;
    const int w = tid >> 5;
    const int l = tid & 31;
    const int jc = rank * 128 + w * 8;
    const int rot = rank * 4;
    const int sub = l & 3;

    // register W: logical c=0..7 -> physical chunk p=(rot+c)&15, k = l+32p
    unsigned long long Wreg[8][4];
#pragma unroll
    for (int c = 0; c < 8; c++) {
        const int p = (rot + c) & 15;
        const float* pw = Whf + (size_t)(l + 32*p) * ND + jc;
        float4 a = *(const float4*)pw;
        float4 b = *(const float4*)(pw + 4);
        asm("mov.b64 %0,{%1,%2};" : "=l"(Wreg[c][0]) : "f"(a.x), "f"(a.y));
        asm("mov.b64 %0,{%1,%2};" : "=l"(Wreg[c][1]) : "f"(a.z), "f"(a.w));
        asm("mov.b64 %0,{%1,%2};" : "=l"(Wreg[c][2]) : "f"(b.x), "f"(b.y));
        asm("mov.b64 %0,{%1,%2};" : "=l"(Wreg[c][3]) : "f"(b.z), "f"(b.w));
    }
    // smem bf16 W: logical c=8..15 -> physical p=(rot+c)&15, slot ((c-8)+l)&7
    const uint32_t wbase = (uint32_t)__cvta_generic_to_shared(wsm) + (uint32_t)tid * 128u;
#pragma unroll
    for (int c = 8; c < 16; c++) {
        const int p = (rot + c) & 15;
        const float* pw = Whf + (size_t)(l + 32*p) * ND + jc;
        float4 a = *(const float4*)pw;
        float4 b = *(const float4*)(pw + 4);
        uint32_t u0 = fpack_bf(a.x, a.y), u1 = fpack_bf(a.z, a.w);
        uint32_t u2 = fpack_bf(b.x, b.y), u3 = fpack_bf(b.z, b.w);
        asm volatile("st.shared.v4.b32 [%0], {%1,%2,%3,%4};"
                     :: "r"(wbase + (uint32_t)((((c - 8) + l) & 7) * 16)),
                        "r"(u0), "r"(u1), "r"(u2), "r"(u3) : "memory");
    }
    hbuf[tid] = 0.f;
    hbuf[tid + 512] = 0.f;

    const uint32_t hbase = (uint32_t)__cvta_generic_to_shared(hbuf);

    // quad-redundant producer state: every lane owns column j = jc + (l>>2)
    const int j = jc + (l >> 2);
    float bj = bhf[j];
    float h_prev = 0.f;
    size_t goff = (size_t)batch * NT * ND + j;
    const float* nhp = nh + goff;
    const float* ifp = ifg + goff;
    float* hop = hout + goff;
    // lane sub stores to rank (rank+sub)&3 ; sub==0 is local (plain STS)
    uint32_t raddr[2];
    if (sub != 0) {
        const int tgt = (rank + sub) & 3;
#pragma unroll
        for (int buf = 0; buf < 2; buf++) {
            uint32_t la = hbase + (uint32_t)((buf * 512 + j) * 4);
            asm("mapa.shared::cluster.u32 %0, %1, %2;"
                : "=r"(raddr[buf]) : "r"(la), "r"(tgt));
        }
    }

    asm volatile("barrier.cluster.arrive.aligned;" ::: "memory");
    asm volatile("barrier.cluster.wait.aligned;"   ::: "memory");

    float nh_cur = nhp[0], if_cur = ifp[0];

    const bool hi16 = (l & 16) != 0;
    const bool hi8  = (l & 8)  != 0;
    const bool hi4  = (l & 4)  != 0;

    // phase-A carry for step 0: h = 0 -> zero partials
    unsigned long long accA0 = 0ull, accA1 = 0ull, accA2 = 0ull, accA3 = 0ull;

    asm volatile("barrier.cluster.arrive.aligned;" ::: "memory");   // open pipeline

    for (int t = 0; t < NT; t++) {
        const int cur = t & 1, nxt = cur ^ 1;
        float nh_nxt = 0.f, if_nxt = 0.f;
        if (t + 1 < NT) {
            nh_nxt = nhp[(size_t)(t+1) * ND];
            if_nxt = ifp[(size_t)(t+1) * ND];
        }
        asm volatile("barrier.cluster.wait.aligned;" ::: "memory");   // h[cur] complete

        const float* hr = hbuf + cur * 512;
        unsigned long long a01 = accA0, a23 = accA1, a45 = accA2, a67 = accA3;
        // phase B: register chunks c=4..7
#pragma unroll
        for (int c = 4; c < 8; c++) {
            float hk = hr[(l + 32 * ((rot + c) & 15))];
            unsigned long long hd;
            asm("mov.b64 %0,{%1,%1};" : "=l"(hd) : "f"(hk));
            asm volatile("fma.rn.f32x2 %0, %1, %2, %0;" : "+l"(a01) : "l"(hd), "l"(Wreg[c][0]));
            asm volatile("fma.rn.f32x2 %0, %1, %2, %0;" : "+l"(a23) : "l"(hd), "l"(Wreg[c][1]));
            asm volatile("fma.rn.f32x2 %0, %1, %2, %0;" : "+l"(a45) : "l"(hd), "l"(Wreg[c][2]));
            asm volatile("fma.rn.f32x2 %0, %1, %2, %0;" : "+l"(a67) : "l"(hd), "l"(Wreg[c][3]));
        }
        // phase B: smem bf16 chunks c=8..15
#pragma unroll
        for (int c = 8; c < 16; c++) {
            float hk = hr[(l + 32 * ((rot + c) & 15))];
            unsigned long long hd;
            asm("mov.b64 %0,{%1,%1};" : "=l"(hd) : "f"(hk));
            uint32_t u0, u1, u2, u3;
            asm volatile("ld.shared.v4.b32 {%0,%1,%2,%3},[%4];"
                         : "=r"(u0), "=r"(u1), "=r"(u2), "=r"(u3)
                         : "r"(wbase + (uint32_t)((((c - 8) + l) & 7) * 16)));
            unsigned long long w0, w1, w2, w3;
            asm("{.reg .b32 lo,hi; shl.b32 lo,%1,16; and.b32 hi,%1,0xffff0000U; mov.b64 %0,{lo,hi};}"
                : "=l"(w0) : "r"(u0));
            asm("{.reg .b32 lo,hi; shl.b32 lo,%1,16; and.b32 hi,%1,0xffff0000U; mov.b64 %0,{lo,hi};}"
                : "=l"(w1) : "r"(u1));
            asm("{.reg .b32 lo,hi; shl.b32 lo,%1,16; and.b32 hi,%1,0xffff0000U; mov.b64 %0,{lo,hi};}"
                : "=l"(w2) : "r"(u2));
            asm("{.reg .b32 lo,hi; shl.b32 lo,%1,16; and.b32 hi,%1,0xffff0000U; mov.b64 %0,{lo,hi};}"
                : "=l"(w3) : "r"(u3));
            asm volatile("fma.rn.f32x2 %0, %1, %2, %0;" : "+l"(a01) : "l"(hd), "l"(w0));
            asm volatile("fma.rn.f32x2 %0, %1, %2, %0;" : "+l"(a23) : "l"(hd), "l"(w1));
            asm volatile("fma.rn.f32x2 %0, %1, %2, %0;" : "+l"(a45) : "l"(hd), "l"(w2));
            asm volatile("fma.rn.f32x2 %0, %1, %2, %0;" : "+l"(a67) : "l"(hd), "l"(w3));
        }
        float a0,a1,a2,a3,a4,a5,a6,a7;
        asm("mov.b64 {%0,%1},%2;" : "=f"(a0), "=f"(a1) : "l"(a01));
        asm("mov.b64 {%0,%1},%2;" : "=f"(a2), "=f"(a3) : "l"(a23));
        asm("mov.b64 {%0,%1},%2;" : "=f"(a4), "=f"(a5) : "l"(a45));
        asm("mov.b64 {%0,%1},%2;" : "=f"(a6), "=f"(a7) : "l"(a67));
        float b0, b1, b2, b3;
        {
            float s0 = hi16 ? a0 : a4, k0 = hi16 ? a4 : a0;
            float s1 = hi16 ? a1 : a5, k1 = hi16 ? a5 : a1;
            float s2 = hi16 ? a2 : a6, k2 = hi16 ? a6 : a2;
            float s3 = hi16 ? a3 : a7, k3 = hi16 ? a7 : a3;
            b0 = k0 + __shfl_xor_sync(0xffffffffu, s0, 16);
            b1 = k1 + __shfl_xor_sync(0xffffffffu, s1, 16);
            b2 = k2 + __shfl_xor_sync(0xffffffffu, s2, 16);
            b3 = k3 + __shfl_xor_sync(0xffffffffu, s3, 16);
        }
        float d0, d1;
        {
            float s0 = hi8 ? b0 : b2, k0 = hi8 ? b2 : b0;
            float s1 = hi8 ? b1 : b3, k1 = hi8 ? b3 : b1;
            d0 = k0 + __shfl_xor_sync(0xffffffffu, s0, 8);
            d1 = k1 + __shfl_xor_sync(0xffffffffu, s1, 8);
        }
        float e;
        {
            float s = hi4 ? d0 : d1, k = hi4 ? d1 : d0;
            e = k + __shfl_xor_sync(0xffffffffu, s, 4);
        }
        e += __shfl_xor_sync(0xffffffffu, e, 2);
        e += __shfl_xor_sync(0xffffffffu, e, 1);
        // ALL 4 quad lanes now hold the identical full sum e for column j.
        float z = e + bj + if_cur;
        float g = 1.f / (1.f + __expf(-z));
        float hn = fmaf(g, nh_cur - h_prev, h_prev);
        h_prev = hn;
        if (sub == 0) {
            hbuf[nxt * 512 + j] = hn;   // local (plain STS, syncthreads-ordered)
        } else {
            asm volatile("st.shared::cluster.f32 [%0], %1;"
                         :: "r"(raddr[nxt]), "f"(hn) : "memory");
        }
        asm volatile("barrier.cluster.arrive.aligned;" ::: "memory");
        if (sub == 0) hop[(size_t)t * ND] = hn;
        nh_cur = nh_nxt; if_cur = if_nxt;
        __syncthreads();   // local h[nxt] visible
        // phase A for step t+1: local chunks c=0..3 (k in [128*rank, 128*rank+128))
        {
            const float* hn_loc = hbuf + nxt * 512;
            accA0 = 0ull; accA1 = 0ull; accA2 = 0ull; accA3 = 0ull;
#pragma unroll
            for (int c = 0; c < 4; c++) {
                float hk = hn_loc[(l + 32 * ((rot + c) & 15))];
                unsigned long long hd;
                asm("mov.b64 %0,{%1,%1};" : "=l"(hd) : "f"(hk));
                asm volatile("fma.rn.f32x2 %0, %1, %2, %0;" : "+l"(accA0) : "l"(hd), "l"(Wreg[c][0]));
                asm volatile("fma.rn.f32x2 %0, %1, %2, %0;" : "+l"(accA1) : "l"(hd), "l"(Wreg[c][1]));
                asm volatile("fma.rn.f32x2 %0, %1, %2, %0;" : "+l"(accA2) : "l"(hd), "l"(Wreg[c][2]));
                asm volatile("fma.rn.f32x2 %0, %1, %2, %0;" : "+l"(accA3) : "l"(hd), "l"(Wreg[c][3]));
            }
        }
    }
    asm volatile("barrier.cluster.wait.aligned;" ::: "memory");   // match final arrive
}

// ---------------- launch ----------------
static void launch_scan(const float* nh, const float* ifb,
                        const float* W, const float* b, float* ho)
{
    constexpr int SMEMB = 65536 + 4096;
    cudaFuncSetAttribute(scan_kernel, cudaFuncAttributeMaxDynamicSharedMemorySize, SMEMB);
    cudaLaunchConfig_t cfg = {};
    cfg.gridDim  = dim3(128, 1, 1);
    cfg.blockDim = dim3(512, 1, 1);
    cfg.dynamicSmemBytes = SMEMB;
    cfg.stream = 0;
    cudaLaunchAttribute attr;
    attr.id = cudaLaunchAttributeClusterDimension;
    attr.val.clusterDim.x = 4; attr.val.clusterDim.y = 1; attr.val.clusterDim.z = 1;
    cfg.attrs = &attr;
    cfg.numAttrs = 1;
    cudaLaunchKernelEx(&cfg, scan_kernel, nh, ifb, W, b, ho);
}

extern "C" void kernel_launch(void* const* d_in, const int* in_sizes, int n_in,
                              void* d_out, int out_size)
{
    const float* x     = (const float*)d_in[0];
    const float* gamma = (const float*)d_in[1];
    const float* gWn   = (const float*)d_in[2];
    const float* gWif  = (const float*)d_in[3];
    const float* gWhf  = (const float*)d_in[4];
    const float* gbhf  = (const float*)d_in[5];
    const float* l0Wn  = (const float*)d_in[6];
    const float* l0Wif = (const float*)d_in[7];
    const float* l0Whf = (const float*)d_in[8];
    const float* l0bhf = (const float*)d_in[9];
    const float* l1Wn  = (const float*)d_in[10];
    const float* l1Wif = (const float*)d_in[11];
    const float* l1Whf = (const float*)d_in[12];
    const float* l1bhf = (const float*)d_in[13];
    float* out = (float*)d_out;

    float *xn, *nh, *ifb, *h0, *h1;
    cudaGetSymbolAddress((void**)&xn,  g_xn);
    cudaGetSymbolAddress((void**)&nh,  g_nh);
    cudaGetSymbolAddress((void**)&ifb, g_ifb);
    cudaGetSymbolAddress((void**)&h0,  g_h0);
    cudaGetSymbolAddress((void**)&h1,  g_h1);

    dim3 gg(NROWS / 128, ND / 128);

    rmsnorm_kernel<<<NROWS / 8, 256>>>(x, gamma, xn);

    tgemm_kernel<1,0><<<gg, 256>>>(xn, l0Wn,  nh,  nullptr, nullptr, nullptr, nullptr);
    tgemm_kernel<0,0><<<gg, 256>>>(xn, l0Wif, ifb, nullptr, nullptr, nullptr, nullptr);
    launch_scan(nh, ifb, l0Whf, l0bhf, h0);

    tgemm_kernel<1,0><<<gg, 256>>>(h0, l1Wn,  nh,  nullptr, nullptr, nullptr, nullptr);
    tgemm_kernel<0,0><<<gg, 256>>>(h0, l1Wif, ifb, nullptr, nullptr, nullptr, nullptr);
    launch_scan(nh, ifb, l1Whf, l1bhf, h1);

    tgemm_kernel<1,0><<<gg, 256>>>(h1, gWn,  nh,  nullptr, nullptr, nullptr, nullptr);
    tgemm_kernel<0,0><<<gg, 256>>>(h1, gWif, ifb, nullptr, nullptr, nullptr, nullptr);
    // fused: hf = xn @ gWhf computed in-register; epilogue does gate-combine + residual
    tgemm_kernel<0,1><<<gg, 256>>>(xn, gWhf, out, x, nh, ifb, gbhf);
}